// round 15
// baseline (speedup 1.0000x reference)
#include <cuda_runtime.h>
#include <cuda_fp16.h>
#include <cstdint>

typedef uint32_t u32;

// ---- f16x2 helpers ----
__device__ __forceinline__ u32 pk16(float lo, float hi) {  // lo -> low half
    u32 r; asm("cvt.rn.f16x2.f32 %0, %1, %2;" : "=r"(r) : "f"(hi), "f"(lo)); return r;
}
__device__ __forceinline__ void up16(u32 p, float& lo, float& hi) {
    asm("{ .reg .b16 l, h; mov.b32 {l, h}, %2; cvt.f32.f16 %0, l; cvt.f32.f16 %1, h; }"
        : "=f"(lo), "=f"(hi) : "r"(p));
}
__device__ __forceinline__ u32 th2(u32 x) {                // 2x tanh, 1 MUFU
    u32 r; asm("tanh.approx.f16x2 %0, %1;" : "=r"(r) : "r"(x)); return r;
}
__device__ __forceinline__ u32 sg2(u32 t) {                // t*0.5+0.5 packed
    u32 r; asm("fma.rn.f16x2 %0, %1, %2, %2;" : "=r"(r) : "r"(t), "r"(0x38003800u)); return r;
}
__device__ __forceinline__ u32 hmul2(u32 a, u32 b) {
    u32 r; asm("mul.rn.f16x2 %0, %1, %2;" : "=r"(r) : "r"(a), "r"(b)); return r;
}
__device__ __forceinline__ u32 hadd2(u32 a, u32 b) {
    u32 r; asm("add.rn.f16x2 %0, %1, %2;" : "=r"(r) : "r"(a), "r"(b)); return r;
}
// f32 value rounded to f16, returned as f32
__device__ __forceinline__ float rh(float v) {
    return __half2float(__float2half_rn(v));
}
// f32 tanh (MUFU) for epilogue-precision path
__device__ __forceinline__ float tanha(float x) {
    float r; asm("tanh.approx.f32 %0, %1;" : "=f"(r) : "f"(x)); return r;
}
__device__ __forceinline__ float sigp(float hz) { return fmaf(tanha(hz), 0.5f, 0.5f); }

// m16n8k16 all-f16 MMA: D (2x f16x2) = A*B + C   (depth-1: fresh D)
__device__ __forceinline__ void mma_h(u32& d0, u32& d1,
                                      u32 a0, u32 a1, u32 a2, u32 a3,
                                      u32 b0, u32 b1, u32 c0, u32 c1) {
    asm("mma.sync.aligned.m16n8k16.row.col.f16.f16.f16.f16 "
        "{%0,%1}, {%2,%3,%4,%5}, {%6,%7}, {%8,%9};"
        : "=r"(d0), "=r"(d1)
        : "r"(a0), "r"(a1), "r"(a2), "r"(a3), "r"(b0), "r"(b1), "r"(c0), "r"(c1));
}

// All-f16x2 LSTM cell, 4 cells: gate preacts arrive as MERGED f16x2 packs.
// i,f,o prescaled by 0.5 => sigmoid = tanh2*0.5+0.5. c is f32.
// h output packs are exactly the next MMA's A-fragment layout.
__device__ __forceinline__ void cell_h(u32 dI0, u32 dI1, u32 dF0, u32 dF1,
                                       u32 dG0, u32 dG1, u32 dO0, u32 dO1,
                                       float* c, u32& hp0, u32& hp1) {
    u32 iv0 = sg2(th2(dI0)), iv1 = sg2(th2(dI1));
    u32 fv0 = sg2(th2(dF0)), fv1 = sg2(th2(dF1));
    u32 gv0 = th2(dG0),      gv1 = th2(dG1);
    u32 ov0 = sg2(th2(dO0)), ov1 = sg2(th2(dO1));
    u32 ig0 = hmul2(iv0, gv0), ig1 = hmul2(iv1, gv1);
    float ia, ib, ic2, id2, fa, fb, fc2, fd2;
    up16(ig0, ia, ib);  up16(ig1, ic2, id2);
    up16(fv0, fa, fb);  up16(fv1, fc2, fd2);
    c[0] = fmaf(fa,  c[0], ia);
    c[1] = fmaf(fb,  c[1], ib);
    c[2] = fmaf(fc2, c[2], ic2);
    c[3] = fmaf(fd2, c[3], id2);
    u32 tc0 = th2(pk16(c[0], c[1]));
    u32 tc1 = th2(pk16(c[2], c[3]));
    hp0 = hmul2(ov0, tc0);
    hp1 = hmul2(ov1, tc1);
}

// One warp = 16 sequences, all-f16 HMMA datapath, DEPTH-1 MMAs ONLY:
//   per layer per gate: d = A x W_hi + bias(C),  e = A x W_lo + 0
//   (independent accumulators; merged with hadd2 at consume time).
// Weights f16 hi+lo (systematic error ~0); h/x single f16.
// Deep pipeline: L0 runs one step ahead of L1 (A: issue L1(t);
// B: consume L0(t+1); C: issue L0(t+2); D: consume L1(t)).
__global__ void __launch_bounds__(128) lstm_hmma2(
    const float* __restrict__ input,
    const float* __restrict__ w_ih0, const float* __restrict__ w_hh0,
    const float* __restrict__ b_ih0, const float* __restrict__ b_hh0,
    const float* __restrict__ w_ih1, const float* __restrict__ w_hh1,
    const float* __restrict__ b_ih1, const float* __restrict__ b_hh1,
    const float* __restrict__ w_mlp, const float* __restrict__ b_mlp,
    float* __restrict__ out, int B)
{
    const int T = 256;
    int lane = threadIdx.x & 31;
    int gid  = lane >> 2;          // B-frag n index / D-A row group
    int tg   = lane & 3;           // k/col pair group
    int warp = (blockIdx.x * (blockDim.x >> 5)) + (threadIdx.x >> 5);
    int wbase = warp * 16;

    int rA = wbase + gid;
    int rB = wbase + gid + 8;
    int rAc = (rA < B) ? rA : (B - 1);
    int rBc = (rB < B) ? rB : (B - 1);

    // ---- weights: f16 hi+lo fragments; i,f,o rows prescaled by 0.5 ----
    u32 B0h0[4], B0h1[4], B0l0[4], B0l1[4];
    u32 B1h0[4], B1h1[4], B1l0[4], B1l1[4];
    u32 cb0[4], cb1[4];
#pragma unroll
    for (int g = 0; g < 4; g++) {
        int wr = g * 8 + gid;
        float s = (g == 2) ? 1.0f : 0.5f;
        // L0 k0-7: w_hh0
        float w0 = s * w_hh0[wr * 8 + 2 * tg], w1 = s * w_hh0[wr * 8 + 2 * tg + 1];
        float w0h = rh(w0), w1h = rh(w1);
        B0h0[g] = pk16(w0h, w1h);
        B0l0[g] = pk16(w0 - w0h, w1 - w1h);
        // L0 k8-15: k8,9 = w_ih0 (tg==0 only), rest 0
        float v0 = 0.f, v1 = 0.f;
        if (tg == 0) { v0 = s * w_ih0[wr * 2]; v1 = s * w_ih0[wr * 2 + 1]; }
        float v0h = rh(v0), v1h = rh(v1);
        B0h1[g] = pk16(v0h, v1h);
        B0l1[g] = pk16(v0 - v0h, v1 - v1h);
        // L1 k0-7: w_ih1 (vs h0), k8-15: w_hh1 (vs h1)
        float u0 = s * w_ih1[wr * 8 + 2 * tg], u1 = s * w_ih1[wr * 8 + 2 * tg + 1];
        float u0h = rh(u0), u1h = rh(u1);
        B1h0[g] = pk16(u0h, u1h);
        B1l0[g] = pk16(u0 - u0h, u1 - u1h);
        float q0 = s * w_hh1[wr * 8 + 2 * tg], q1 = s * w_hh1[wr * 8 + 2 * tg + 1];
        float q0h = rh(q0), q1h = rh(q1);
        B1h1[g] = pk16(q0h, q1h);
        B1l1[g] = pk16(q0 - q0h, q1 - q1h);
        // biases as f16x2 C operand (D cols 2tg, 2tg+1)
        int cE = g * 8 + 2 * tg;
        cb0[g] = pk16(s * (b_ih0[cE] + b_hh0[cE]), s * (b_ih0[cE + 1] + b_hh0[cE + 1]));
        cb1[g] = pk16(s * (b_ih1[cE] + b_hh1[cE]), s * (b_ih1[cE + 1] + b_hh1[cE + 1]));
    }

    // ---- state ----
    float c0[4] = {0.f, 0.f, 0.f, 0.f};
    float c1[4] = {0.f, 0.f, 0.f, 0.f};
    u32 h0p0 = 0, h0p1 = 0, h1p0 = 0, h1p1 = 0;
    u32 d0a[4], d0b[4], e0a[4], e0b[4];
    u32 d1a[4], d1b[4], e1a[4], e1b[4];

    const float2* xr = reinterpret_cast<const float2*>(input);
    auto xsel = [&](float2 x) -> u32 { return (tg == 0) ? pk16(x.x, x.y) : 0u; };

    // issue L0 step: two INDEPENDENT depth-1 MMAs per gate
    auto issueL0 = [&](u32 xa2, u32 xa3) {
#pragma unroll
        for (int g = 0; g < 4; g++) {
            mma_h(d0a[g], d0b[g], h0p0, h0p1, xa2, xa3, B0h0[g], B0h1[g], cb0[g], cb0[g]);
            mma_h(e0a[g], e0b[g], h0p0, h0p1, xa2, xa3, B0l0[g], B0l1[g], 0u, 0u);
        }
    };

    // ---- prologue ----
    {
        // L0(0) with h0(-1)=0
        float2 xA = __ldg(&xr[(size_t)rAc * T]);
        float2 xB = __ldg(&xr[(size_t)rBc * T]);
        issueL0(xsel(xA), xsel(xB));
        // consume -> h0(0)
        cell_h(hadd2(d0a[0], e0a[0]), hadd2(d0b[0], e0b[0]),
               hadd2(d0a[1], e0a[1]), hadd2(d0b[1], e0b[1]),
               hadd2(d0a[2], e0a[2]), hadd2(d0b[2], e0b[2]),
               hadd2(d0a[3], e0a[3]), hadd2(d0b[3], e0b[3]),
               c0, h0p0, h0p1);
        // issue L0(1)
        xA = __ldg(&xr[(size_t)rAc * T + 1]);
        xB = __ldg(&xr[(size_t)rBc * T + 1]);
        issueL0(xsel(xA), xsel(xB));
    }

    for (int t = 0; t < T; t++) {
        // ---- A: issue L1(t) using h0(t), h1(t-1) — 2 indep depth-1 MMAs ----
#pragma unroll
        for (int g = 0; g < 4; g++) {
            mma_h(d1a[g], d1b[g], h0p0, h0p1, h1p0, h1p1, B1h0[g], B1h1[g], cb1[g], cb1[g]);
            mma_h(e1a[g], e1b[g], h0p0, h0p1, h1p0, h1p1, B1l0[g], B1l1[g], 0u, 0u);
        }

        // ---- B: consume L0(t+1) -> h0(t+1)  (covers A's MMA latency) ----
        cell_h(hadd2(d0a[0], e0a[0]), hadd2(d0b[0], e0b[0]),
               hadd2(d0a[1], e0a[1]), hadd2(d0b[1], e0b[1]),
               hadd2(d0a[2], e0a[2]), hadd2(d0b[2], e0b[2]),
               hadd2(d0a[3], e0a[3]), hadd2(d0b[3], e0b[3]),
               c0, h0p0, h0p1);

        // ---- C: issue L0(t+2) using h0(t+1) ----
        {
            int tn = (t + 2 < T) ? (t + 2) : (T - 1);
            float2 xA = __ldg(&xr[(size_t)rAc * T + tn]);
            float2 xB = __ldg(&xr[(size_t)rBc * T + tn]);
            issueL0(xsel(xA), xsel(xB));
        }

        // ---- D: consume L1(t) -> h1(t) ----
        u32 gI0 = hadd2(d1a[0], e1a[0]), gI1 = hadd2(d1b[0], e1b[0]);
        u32 gF0 = hadd2(d1a[1], e1a[1]), gF1 = hadd2(d1b[1], e1b[1]);
        u32 gG0 = hadd2(d1a[2], e1a[2]), gG1 = hadd2(d1b[2], e1b[2]);
        u32 gO0 = hadd2(d1a[3], e1a[3]), gO1 = hadd2(d1b[3], e1b[3]);
        if (t < T - 1) {
            cell_h(gI0, gI1, gF0, gF1, gG0, gG1, gO0, gO1, c1, h1p0, h1p1);
        } else {
            // final step: update c1 only; h1(T-1) recomputed in f32 below
            u32 iv0 = sg2(th2(gI0)), iv1 = sg2(th2(gI1));
            u32 fv0 = sg2(th2(gF0)), fv1 = sg2(th2(gF1));
            u32 gv0 = th2(gG0),      gv1 = th2(gG1);
            u32 ig0 = hmul2(iv0, gv0), ig1 = hmul2(iv1, gv1);
            float ia, ib, ic2, id2, fa, fb, fc2, fd2;
            up16(ig0, ia, ib);  up16(ig1, ic2, id2);
            up16(fv0, fa, fb);  up16(fv1, fc2, fd2);
            c1[0] = fmaf(fa,  c1[0], ia);
            c1[1] = fmaf(fb,  c1[1], ib);
            c1[2] = fmaf(fc2, c1[2], ic2);
            c1[3] = fmaf(fd2, c1[3], id2);
            d1a[3] = gO0; d1b[3] = gO1;   // stash merged o-gate for epilogue
        }
    }

    // ---- final h1 in f32 (o-gate preacts, f32 c1) ----
    float h1f[4];
    {
        float o0, o1, o2, o3;
        up16(d1a[3], o0, o1);
        up16(d1b[3], o2, o3);
        h1f[0] = sigp(o0) * tanha(c1[0]);
        h1f[1] = sigp(o1) * tanha(c1[1]);
        h1f[2] = sigp(o2) * tanha(c1[2]);
        h1f[3] = sigp(o3) * tanha(c1[3]);
    }

    // ================= MLP head =================
    int hidE = tg * 2;
    float w0e = w_mlp[hidE],     w0o = w_mlp[hidE + 1];
    float w1e = w_mlp[8 + hidE], w1o = w_mlp[8 + hidE + 1];
    float p0A = h1f[0] * w0e + h1f[1] * w0o;
    float p1A = h1f[0] * w1e + h1f[1] * w1o;
    float p0B = h1f[2] * w0e + h1f[3] * w0o;
    float p1B = h1f[2] * w1e + h1f[3] * w1o;
#pragma unroll
    for (int off = 1; off < 4; off <<= 1) {
        p0A += __shfl_xor_sync(0xffffffffu, p0A, off);
        p1A += __shfl_xor_sync(0xffffffffu, p1A, off);
        p0B += __shfl_xor_sync(0xffffffffu, p0B, off);
        p1B += __shfl_xor_sync(0xffffffffu, p1B, off);
    }
    if (tg == 0) {
        if (rA < B) {
            float2 o; o.x = p0A + b_mlp[0]; o.y = p1A + b_mlp[1];
            reinterpret_cast<float2*>(out)[rA] = o;
        }
        if (rB < B) {
            float2 o; o.x = p0B + b_mlp[0]; o.y = p1B + b_mlp[1];
            reinterpret_cast<float2*>(out)[rB] = o;
        }
    }
}

extern "C" void kernel_launch(void* const* d_in, const int* in_sizes, int n_in,
                              void* d_out, int out_size) {
    const float* input = (const float*)d_in[0];
    const float* w_ih0 = (const float*)d_in[1];
    const float* w_hh0 = (const float*)d_in[2];
    const float* b_ih0 = (const float*)d_in[3];
    const float* b_hh0 = (const float*)d_in[4];
    const float* w_ih1 = (const float*)d_in[5];
    const float* w_hh1 = (const float*)d_in[6];
    const float* b_ih1 = (const float*)d_in[7];
    const float* b_hh1 = (const float*)d_in[8];
    const float* w_mlp = (const float*)d_in[9];
    const float* b_mlp = (const float*)d_in[10];

    const int T = 256, IN = 2;
    int B = in_sizes[0] / (T * IN);

    int grid = (B + 63) / 64;      // 16 seqs/warp, 4 warps/block
    lstm_hmma2<<<grid, 128>>>(input, w_ih0, w_hh0, b_ih0, b_hh0,
                              w_ih1, w_hh1, b_ih1, b_hh1,
                              w_mlp, b_mlp, (float*)d_out, B);
}

// round 16
// speedup vs baseline: 1.0466x; 1.0466x over previous
#include <cuda_runtime.h>
#include <cuda_fp16.h>
#include <cstdint>

typedef uint32_t u32;

// ---- f16x2 helpers ----
__device__ __forceinline__ u32 pk16(float lo, float hi) {  // lo -> low half
    u32 r; asm("cvt.rn.f16x2.f32 %0, %1, %2;" : "=r"(r) : "f"(hi), "f"(lo)); return r;
}
__device__ __forceinline__ void up16(u32 p, float& lo, float& hi) {
    asm("{ .reg .b16 l, h; mov.b32 {l, h}, %2; cvt.f32.f16 %0, l; cvt.f32.f16 %1, h; }"
        : "=f"(lo), "=f"(hi) : "r"(p));
}
__device__ __forceinline__ u32 th2(u32 x) {                // 2x tanh, 1 MUFU
    u32 r; asm("tanh.approx.f16x2 %0, %1;" : "=r"(r) : "r"(x)); return r;
}
__device__ __forceinline__ u32 sg2(u32 t) {                // t*0.5+0.5 packed
    u32 r; asm("fma.rn.f16x2 %0, %1, %2, %2;" : "=r"(r) : "r"(t), "r"(0x38003800u)); return r;
}
__device__ __forceinline__ u32 hmul2(u32 a, u32 b) {
    u32 r; asm("mul.rn.f16x2 %0, %1, %2;" : "=r"(r) : "r"(a), "r"(b)); return r;
}
// f32 tanh (MUFU) for epilogue-precision path
__device__ __forceinline__ float tanha(float x) {
    float r; asm("tanh.approx.f32 %0, %1;" : "=f"(r) : "f"(x)); return r;
}
__device__ __forceinline__ float sigp(float hz) { return fmaf(tanha(hz), 0.5f, 0.5f); }

// m16n8k16 all-f16 MMA: D (2x f16x2) = A*B + C  (always depth-1)
__device__ __forceinline__ void mma_h(u32& d0, u32& d1,
                                      u32 a0, u32 a1, u32 a2, u32 a3,
                                      u32 b0, u32 b1, u32 c0, u32 c1) {
    asm("mma.sync.aligned.m16n8k16.row.col.f16.f16.f16.f16 "
        "{%0,%1}, {%2,%3,%4,%5}, {%6,%7}, {%8,%9};"
        : "=r"(d0), "=r"(d1)
        : "r"(a0), "r"(a1), "r"(a2), "r"(a3), "r"(b0), "r"(b1), "r"(c0), "r"(c1));
}

// All-f16x2 LSTM cell, 4 cells: gate preacts arrive as f16x2 MMA D regs
// (i,f,o prescaled by 0.5 => sigmoid = tanh2*0.5+0.5). c is f32.
// h output packs are exactly the next MMA's A-fragment layout.
__device__ __forceinline__ void cell_h(u32 dI0, u32 dI1, u32 dF0, u32 dF1,
                                       u32 dG0, u32 dG1, u32 dO0, u32 dO1,
                                       float* c, u32& hp0, u32& hp1) {
    u32 iv0 = sg2(th2(dI0)), iv1 = sg2(th2(dI1));
    u32 fv0 = sg2(th2(dF0)), fv1 = sg2(th2(dF1));
    u32 gv0 = th2(dG0),      gv1 = th2(dG1);
    u32 ov0 = sg2(th2(dO0)), ov1 = sg2(th2(dO1));
    u32 ig0 = hmul2(iv0, gv0), ig1 = hmul2(iv1, gv1);
    float ia, ib, ic2, id2, fa, fb, fc2, fd2;
    up16(ig0, ia, ib);  up16(ig1, ic2, id2);
    up16(fv0, fa, fb);  up16(fv1, fc2, fd2);
    c[0] = fmaf(fa,  c[0], ia);
    c[1] = fmaf(fb,  c[1], ib);
    c[2] = fmaf(fc2, c[2], ic2);
    c[3] = fmaf(fd2, c[3], id2);
    u32 tc0 = th2(pk16(c[0], c[1]));
    u32 tc1 = th2(pk16(c[2], c[3]));
    hp0 = hmul2(ov0, tc0);
    hp1 = hmul2(ov1, tc1);
}

// One warp = 16 sequences, all-f16 HMMA datapath, ONE depth-1 MMA per gate
// per layer (f16 weights; W-lo corrections dropped — f16 truncation is 8x
// finer than bf16, adding only ~5e-5 systematic error).
// Deep pipeline: L0 runs one step ahead of L1:
//   A: issue L1(t); B: consume L0(t+1); C: issue L0(t+2); D: consume L1(t).
__global__ void __launch_bounds__(128) lstm_hmma3(
    const float* __restrict__ input,
    const float* __restrict__ w_ih0, const float* __restrict__ w_hh0,
    const float* __restrict__ b_ih0, const float* __restrict__ b_hh0,
    const float* __restrict__ w_ih1, const float* __restrict__ w_hh1,
    const float* __restrict__ b_ih1, const float* __restrict__ b_hh1,
    const float* __restrict__ w_mlp, const float* __restrict__ b_mlp,
    float* __restrict__ out, int B)
{
    const int T = 256;
    int lane = threadIdx.x & 31;
    int gid  = lane >> 2;          // B-frag n index / D-A row group
    int tg   = lane & 3;           // k/col pair group
    int warp = (blockIdx.x * (blockDim.x >> 5)) + (threadIdx.x >> 5);
    int wbase = warp * 16;

    int rA = wbase + gid;
    int rB = wbase + gid + 8;
    int rAc = (rA < B) ? rA : (B - 1);
    int rBc = (rB < B) ? rB : (B - 1);

    // ---- weights: single f16 fragments; i,f,o rows prescaled by 0.5 ----
    u32 B00[4], B01[4], B10[4], B11[4], cb0[4], cb1[4];
#pragma unroll
    for (int g = 0; g < 4; g++) {
        int wr = g * 8 + gid;
        float s = (g == 2) ? 1.0f : 0.5f;
        // L0: k0-7 = w_hh0; k8,9 = w_ih0 (tg==0), rest 0
        B00[g] = pk16(s * w_hh0[wr * 8 + 2 * tg], s * w_hh0[wr * 8 + 2 * tg + 1]);
        float v0 = 0.f, v1 = 0.f;
        if (tg == 0) { v0 = s * w_ih0[wr * 2]; v1 = s * w_ih0[wr * 2 + 1]; }
        B01[g] = pk16(v0, v1);
        // L1: k0-7 = w_ih1 (vs h0); k8-15 = w_hh1 (vs h1)
        B10[g] = pk16(s * w_ih1[wr * 8 + 2 * tg], s * w_ih1[wr * 8 + 2 * tg + 1]);
        B11[g] = pk16(s * w_hh1[wr * 8 + 2 * tg], s * w_hh1[wr * 8 + 2 * tg + 1]);
        // biases as f16x2 C operand (D cols 2tg, 2tg+1)
        int cE = g * 8 + 2 * tg;
        cb0[g] = pk16(s * (b_ih0[cE] + b_hh0[cE]), s * (b_ih0[cE + 1] + b_hh0[cE + 1]));
        cb1[g] = pk16(s * (b_ih1[cE] + b_hh1[cE]), s * (b_ih1[cE + 1] + b_hh1[cE + 1]));
    }

    // ---- state ----
    float c0[4] = {0.f, 0.f, 0.f, 0.f};
    float c1[4] = {0.f, 0.f, 0.f, 0.f};
    u32 h0p0 = 0, h0p1 = 0, h1p0 = 0, h1p1 = 0;
    u32 d0a[4], d0b[4], d1a[4], d1b[4];

    const float2* xr = reinterpret_cast<const float2*>(input);
    auto xsel = [&](float2 x) -> u32 { return (tg == 0) ? pk16(x.x, x.y) : 0u; };

    // ---- prologue ----
    {
        // L0(0) with h0(-1)=0
        float2 xA = __ldg(&xr[(size_t)rAc * T]);
        float2 xB = __ldg(&xr[(size_t)rBc * T]);
        u32 xa2 = xsel(xA), xa3 = xsel(xB);
#pragma unroll
        for (int g = 0; g < 4; g++)
            mma_h(d0a[g], d0b[g], 0u, 0u, xa2, xa3, B00[g], B01[g], cb0[g], cb0[g]);
        cell_h(d0a[0], d0b[0], d0a[1], d0b[1], d0a[2], d0b[2], d0a[3], d0b[3],
               c0, h0p0, h0p1);
        // issue L0(1)
        xA = __ldg(&xr[(size_t)rAc * T + 1]);
        xB = __ldg(&xr[(size_t)rBc * T + 1]);
        xa2 = xsel(xA); xa3 = xsel(xB);
#pragma unroll
        for (int g = 0; g < 4; g++)
            mma_h(d0a[g], d0b[g], h0p0, h0p1, xa2, xa3, B00[g], B01[g], cb0[g], cb0[g]);
    }

    for (int t = 0; t < T; t++) {
        // ---- A: issue L1(t) using h0(t), h1(t-1) — 1 depth-1 MMA/gate ----
#pragma unroll
        for (int g = 0; g < 4; g++)
            mma_h(d1a[g], d1b[g], h0p0, h0p1, h1p0, h1p1, B10[g], B11[g], cb1[g], cb1[g]);

        // ---- B: consume L0(t+1) -> h0(t+1)  (covers A's MMA latency) ----
        cell_h(d0a[0], d0b[0], d0a[1], d0b[1], d0a[2], d0b[2], d0a[3], d0b[3],
               c0, h0p0, h0p1);

        // ---- C: issue L0(t+2) using h0(t+1) ----
        {
            int tn = (t + 2 < T) ? (t + 2) : (T - 1);
            float2 xA = __ldg(&xr[(size_t)rAc * T + tn]);
            float2 xB = __ldg(&xr[(size_t)rBc * T + tn]);
            u32 xa2 = xsel(xA), xa3 = xsel(xB);
#pragma unroll
            for (int g = 0; g < 4; g++)
                mma_h(d0a[g], d0b[g], h0p0, h0p1, xa2, xa3, B00[g], B01[g], cb0[g], cb0[g]);
        }

        // ---- D: consume L1(t) -> h1(t) ----
        if (t < T - 1) {
            cell_h(d1a[0], d1b[0], d1a[1], d1b[1], d1a[2], d1b[2], d1a[3], d1b[3],
                   c1, h1p0, h1p1);
        } else {
            // final step: update c1 only; h1(T-1) recomputed in f32 below
            u32 iv0 = sg2(th2(d1a[0])), iv1 = sg2(th2(d1b[0]));
            u32 fv0 = sg2(th2(d1a[1])), fv1 = sg2(th2(d1b[1]));
            u32 gv0 = th2(d1a[2]),      gv1 = th2(d1b[2]);
            u32 ig0 = hmul2(iv0, gv0),  ig1 = hmul2(iv1, gv1);
            float ia, ib, ic2, id2, fa, fb, fc2, fd2;
            up16(ig0, ia, ib);  up16(ig1, ic2, id2);
            up16(fv0, fa, fb);  up16(fv1, fc2, fd2);
            c1[0] = fmaf(fa,  c1[0], ia);
            c1[1] = fmaf(fb,  c1[1], ib);
            c1[2] = fmaf(fc2, c1[2], ic2);
            c1[3] = fmaf(fd2, c1[3], id2);
        }
    }

    // ---- final h1 in f32 (o-gate preacts from last d1, f32 c1) ----
    float h1f[4];
    {
        float o0, o1, o2, o3;
        up16(d1a[3], o0, o1);
        up16(d1b[3], o2, o3);
        h1f[0] = sigp(o0) * tanha(c1[0]);
        h1f[1] = sigp(o1) * tanha(c1[1]);
        h1f[2] = sigp(o2) * tanha(c1[2]);
        h1f[3] = sigp(o3) * tanha(c1[3]);
    }

    // ================= MLP head =================
    int hidE = tg * 2;
    float w0e = w_mlp[hidE],     w0o = w_mlp[hidE + 1];
    float w1e = w_mlp[8 + hidE], w1o = w_mlp[8 + hidE + 1];
    float p0A = h1f[0] * w0e + h1f[1] * w0o;
    float p1A = h1f[0] * w1e + h1f[1] * w1o;
    float p0B = h1f[2] * w0e + h1f[3] * w0o;
    float p1B = h1f[2] * w1e + h1f[3] * w1o;
#pragma unroll
    for (int off = 1; off < 4; off <<= 1) {
        p0A += __shfl_xor_sync(0xffffffffu, p0A, off);
        p1A += __shfl_xor_sync(0xffffffffu, p1A, off);
        p0B += __shfl_xor_sync(0xffffffffu, p0B, off);
        p1B += __shfl_xor_sync(0xffffffffu, p1B, off);
    }
    if (tg == 0) {
        if (rA < B) {
            float2 o; o.x = p0A + b_mlp[0]; o.y = p1A + b_mlp[1];
            reinterpret_cast<float2*>(out)[rA] = o;
        }
        if (rB < B) {
            float2 o; o.x = p0B + b_mlp[0]; o.y = p1B + b_mlp[1];
            reinterpret_cast<float2*>(out)[rB] = o;
        }
    }
}

extern "C" void kernel_launch(void* const* d_in, const int* in_sizes, int n_in,
                              void* d_out, int out_size) {
    const float* input = (const float*)d_in[0];
    const float* w_ih0 = (const float*)d_in[1];
    const float* w_hh0 = (const float*)d_in[2];
    const float* b_ih0 = (const float*)d_in[3];
    const float* b_hh0 = (const float*)d_in[4];
    const float* w_ih1 = (const float*)d_in[5];
    const float* w_hh1 = (const float*)d_in[6];
    const float* b_ih1 = (const float*)d_in[7];
    const float* b_hh1 = (const float*)d_in[8];
    const float* w_mlp = (const float*)d_in[9];
    const float* b_mlp = (const float*)d_in[10];

    const int T = 256, IN = 2;
    int B = in_sizes[0] / (T * IN);

    int grid = (B + 63) / 64;      // 16 seqs/warp, 4 warps/block
    lstm_hmma3<<<grid, 128>>>(input, w_ih0, w_hh0, b_ih0, b_hh0,
                              w_ih1, w_hh1, b_ih1, b_hh1,
                              w_mlp, b_mlp, (float*)d_out, B);
}